// round 7
// baseline (speedup 1.0000x reference)
#include <cuda_runtime.h>

// UnPooling: stride-2 zero-insertion unpool.
// in:  [B=32, H=112, W=112, C=64] fp32
// out: [B=32, 224, 224, 64] fp32; out[b, 2h, 2w, c] = in[b, h, w, c], else 0.
//
// R2 structure (best so far: output-driven, linear store stream, odd-row
// zero-fill fast path) upgraded to 256-bit accesses (sm_100a+ v8.f32):
//   - one 32B chunk per thread; warp stores 1024B in ONE STG.E.256
//   - even-row loads: 16 active lanes x 32B = one contiguous 512B request
// Grid (7, 224, 32): x = 256-chunk of the row (7*256 = 1792 = 224*8 v8/row),
// y = output row, z = batch. No bounds checks needed.

constexpr int B     = 32;
constexpr int H     = 112;
constexpr int OH    = 224;
constexpr int ROWF  = 224 * 64;    // floats per output row (14336)
constexpr int IROWF = 112 * 64;    // floats per input row  (7168)
constexpr int ROW8  = ROWF / 8;    // 1792 v8-chunks per output row

__device__ __forceinline__ void st256_cs(float* p, float v0, float v1, float v2, float v3,
                                         float v4, float v5, float v6, float v7)
{
    asm volatile("st.global.cs.v8.f32 [%0], {%1,%2,%3,%4,%5,%6,%7,%8};"
                 :: "l"(p), "f"(v0), "f"(v1), "f"(v2), "f"(v3),
                    "f"(v4), "f"(v5), "f"(v6), "f"(v7)
                 : "memory");
}

__global__ void __launch_bounds__(256)
unpool_zi_kernel(const float* __restrict__ in, float* __restrict__ out)
{
    const unsigned j  = blockIdx.x * 256u + threadIdx.x;  // v8 index in row, 0..1791
    const unsigned oh = blockIdx.y;
    const unsigned b  = blockIdx.z;

    float* optr = out + (size_t)(b * OH + oh) * ROWF + (size_t)j * 8u;

    float v0 = 0.f, v1 = 0.f, v2 = 0.f, v3 = 0.f,
          v4 = 0.f, v5 = 0.f, v6 = 0.f, v7 = 0.f;

    if (!(oh & 1u)) {
        const unsigned ow = j >> 3;        // output pixel (8 v8-chunks/pixel)
        const unsigned c8 = j & 7u;        // 32B chunk within the pixel
        if (!(ow & 1u)) {
            const float* iptr = in + (size_t)(b * H + (oh >> 1)) * IROWF
                                   + (size_t)((ow >> 1) * 64u + c8 * 8u);
            asm volatile("ld.global.cs.v8.f32 {%0,%1,%2,%3,%4,%5,%6,%7}, [%8];"
                         : "=f"(v0), "=f"(v1), "=f"(v2), "=f"(v3),
                           "=f"(v4), "=f"(v5), "=f"(v6), "=f"(v7)
                         : "l"(iptr));
        }
    }

    st256_cs(optr, v0, v1, v2, v3, v4, v5, v6, v7);
}

extern "C" void kernel_launch(void* const* d_in, const int* in_sizes, int n_in,
                              void* d_out, int out_size)
{
    const float* in  = (const float*)d_in[0];
    float*       out = (float*)d_out;

    dim3 grid(ROW8 / 256, OH, B);   // (7, 224, 32)
    unpool_zi_kernel<<<grid, 256>>>(in, out);
}

// round 8
// speedup vs baseline: 1.0760x; 1.0760x over previous
#include <cuda_runtime.h>

// UnPooling: stride-2 zero-insertion unpool. FINAL (R2 shape).
// in:  [B=32, H=112, W=112, C=64] fp32
// out: [B=32, 224, 224, 64] fp32; out[b, 2h, 2w, c] = in[b, h, w, c], else 0.
//
// Output-driven mapping; the 411MB store stream is perfectly linear per warp.
// Grid (7, 224, 32): x = 512-float4 chunk of the output row, y = output row,
// z = batch. Odd rows: pure zero-fill fast path (no loads, no index math).
// Even rows: 2 float4 per thread, loads predicated on even output pixel.
//
// Session findings (why this shape and nothing else):
//  - 128-bit accesses are optimal: v8/256-bit stores inflate L1tex wavefronts
//    (DRAM% 77 -> 65, L1% 56 -> 82). Same failure for input-driven scatter
//    whose stores interleave even/odd pixel segments.
//  - Store cache policy (.cs vs default) is neutral: output is 3.3x L2.
//  - Extra store MLP per thread (4-store row-pair) is neutral-to-worse:
//    MWC/LTS queues already saturated by occupancy.
//  - Pinned at ~457MB effective traffic @ ~6.1TB/s (77% DRAM) = the mixed
//    R/W HBM turnaround ceiling for this pattern.

constexpr int B     = 32;
constexpr int H     = 112;
constexpr int C4    = 16;          // 64 floats = 16 float4 per pixel
constexpr int OH    = 224;
constexpr int ROW4  = 224 * C4;    // 3584 float4 per output row
constexpr int IROW4 = 112 * C4;    // 1792 float4 per input row
constexpr int CHUNK = 512;         // float4 per block (2 per thread)

__global__ void __launch_bounds__(256)
unpool_zi_kernel(const float4* __restrict__ in, float4* __restrict__ out)
{
    const unsigned tid  = threadIdx.x;
    const unsigned oh   = blockIdx.y;
    const unsigned b    = blockIdx.z;
    const unsigned base = blockIdx.x * (unsigned)CHUNK + tid;

    float4* orow = out + (size_t)(b * OH + oh) * ROW4;

    const float4 z = make_float4(0.f, 0.f, 0.f, 0.f);

    if (oh & 1u) {
        // Entire row is zero: pure streaming store, no loads.
        __stcs(orow + base,        z);
        __stcs(orow + base + 256u, z);
        return;
    }

    const float4* irow = in + (size_t)(b * H + (oh >> 1)) * IROW4;

    const unsigned j0 = base;
    const unsigned j1 = base + 256u;

    const unsigned ow0 = j0 >> 4, c40 = j0 & 15u;
    const unsigned ow1 = j1 >> 4, c41 = j1 & 15u;

    float4 v0 = z, v1 = z;
    if (!(ow0 & 1u)) v0 = __ldcs(irow + (ow0 >> 1) * C4 + c40);
    if (!(ow1 & 1u)) v1 = __ldcs(irow + (ow1 >> 1) * C4 + c41);

    __stcs(orow + j0, v0);
    __stcs(orow + j1, v1);
}

extern "C" void kernel_launch(void* const* d_in, const int* in_sizes, int n_in,
                              void* d_out, int out_size)
{
    const float4* in  = (const float4*)d_in[0];
    float4*       out = (float4*)d_out;

    dim3 grid(ROW4 / CHUNK, OH, B);   // (7, 224, 32)
    unpool_zi_kernel<<<grid, 256>>>(in, out);
}